// round 4
// baseline (speedup 1.0000x reference)
#include <cuda_runtime.h>
#include <cstdint>

// Bilinear attention, B=16, T=D=1024:
//   qW = query @ W ; logits = qW @ keys^T + mask ; score = softmax(logits) ; ctx = score @ values
// GEMMs via mma.sync.m16n8k8 tf32, error-compensated split (hi/lo), fp32 accumulate.
// 256 threads/CTA, 128x128 tile, warp tile 64x32, 3-stage cp.async ring,
// double-buffered fragments so MMAs overlap the barrier + LDS/split phase.

#define NDIM 1024

// Scratch for qW: 16384 x 1024 f32 (static device array: allocation-guard safe)
__device__ float g_qW[16777216];

// ---- helpers -------------------------------------------------------------
static __device__ __forceinline__ uint32_t smem_u32(const void* p) {
    uint32_t a;
    asm("{ .reg .u64 t; cvta.to.shared.u64 t, %1; cvt.u32.u64 %0, t; }" : "=r"(a) : "l"(p));
    return a;
}
static __device__ __forceinline__ uint32_t f2tf32(float a) {
    uint32_t r;
    asm("cvt.rna.tf32.f32 %0, %1;" : "=r"(r) : "f"(a));
    return r;
}
static __device__ __forceinline__ void splitu(float a, uint32_t& h, uint32_t& l) {
    h = f2tf32(a);
    l = f2tf32(a - __uint_as_float(h));
}
static __device__ __forceinline__ void cpa16(uint32_t dst, const void* src) {
    asm volatile("cp.async.ca.shared.global [%0], [%1], 16;" :: "r"(dst), "l"(src));
}
static __device__ __forceinline__ void cp_commit() {
    asm volatile("cp.async.commit_group;" ::: "memory");
}
static __device__ __forceinline__ void cp_wait1() {
    asm volatile("cp.async.wait_group 1;" ::: "memory");
}
static __device__ __forceinline__ void mma8(float* d, const uint32_t* a, const uint32_t* b) {
    asm volatile(
        "mma.sync.aligned.m16n8k8.row.col.f32.tf32.tf32.f32 "
        "{%0,%1,%2,%3}, {%4,%5,%6,%7}, {%8,%9}, {%0,%1,%2,%3};"
        : "+f"(d[0]), "+f"(d[1]), "+f"(d[2]), "+f"(d[3])
        : "r"(a[0]), "r"(a[1]), "r"(a[2]), "r"(a[3]), "r"(b[0]), "r"(b[1]));
}

// ---- SMEM layout (raw f32 tiles, 3 stages) -------------------------------
// Stage: A 128x16 @ stride 20 (2560 f); B 2560 f (NT: 128x16 @20, NN: 16x128 @136)
#define STAGES 3
#define A_OFF(s) ((s) * 5120)
#define B_OFF(s) ((s) * 5120 + 2560)
static constexpr int SMEM_BYTES = STAGES * 5120 * 4;   // 61440

// TERMS==3: Ahi*Bhi + Ahi*Blo + Alo*Bhi (near-fp32; for the logit path)
// TERMS==2: Ahi*Bhi + Alo*Bhi            (full-A x tf32-B; post-softmax GEMM)
template<bool TRANSB, bool ADDMASK, int TERMS>
__global__ __launch_bounds__(256) void gemm_tc_kernel(
    const float* __restrict__ A, const float* __restrict__ B,
    float* __restrict__ C, const float* __restrict__ mask,
    size_t sA, size_t sB, size_t sC)
{
    extern __shared__ float sm[];
    const uint32_t su = smem_u32(sm);
    const int tid = threadIdx.x, wid = tid >> 5, lid = tid & 31;
    const int g = lid >> 2, tg = lid & 3;           // mma group / thread-in-group
    const int wm = (wid >> 2) * 64, wn = (wid & 3) * 32;   // 2x4 warp grid, 64x32 tiles
    const int M0 = blockIdx.y * 128, N0 = blockIdx.x * 128;
    const size_t b = blockIdx.z;
    A += b * sA; B += b * sB; C += b * sC;
    const float* mp = ADDMASK ? (mask + b * 1024) : nullptr;

    // producer geometry (256 threads): A/NT-B: 64 rows x 16 cols per pass, 2 passes
    const int ar = tid >> 2, acol = (tid & 3) << 2;
    // NN-B: 16 rows x 64 cols per pass, 2 passes
    const int bkr = tid >> 4, bcol = (tid & 15) << 2;

    float acc[4][4][4];
    #pragma unroll
    for (int mi = 0; mi < 4; mi++)
        #pragma unroll
        for (int ni = 0; ni < 4; ni++)
            #pragma unroll
            for (int r = 0; r < 4; r++) acc[mi][ni][r] = 0.0f;

    // double-buffered fragments
    uint32_t ah[2][4][4], al[2][4][4], bh[2][4][2], bl[2][4][2];

    auto issue = [&](int c) {
        const int st = c % STAGES;
        const int k0 = c << 4;
        #pragma unroll
        for (int p = 0; p < 2; p++)
            cpa16(su + (A_OFF(st) + (ar + 64 * p) * 20 + acol) * 4,
                  A + (size_t)(M0 + ar + 64 * p) * NDIM + k0 + acol);
        if (TRANSB) {
            #pragma unroll
            for (int p = 0; p < 2; p++)
                cpa16(su + (B_OFF(st) + (ar + 64 * p) * 20 + acol) * 4,
                      B + (size_t)(N0 + ar + 64 * p) * NDIM + k0 + acol);
        } else {
            #pragma unroll
            for (int p = 0; p < 2; p++)
                cpa16(su + (B_OFF(st) + bkr * 136 + bcol + 64 * p) * 4,
                      B + (size_t)(k0 + bkr) * NDIM + N0 + bcol + 64 * p);
        }
        cp_commit();
    };

    auto load_frags = [&](int bi, const float* As, const float* Bs, int ks) {
        #pragma unroll
        for (int mi = 0; mi < 4; mi++) {
            const int r0 = wm + mi * 16 + g;
            const int c0 = ks + tg;
            splitu(As[r0 * 20 + c0],           ah[bi][mi][0], al[bi][mi][0]);
            splitu(As[(r0 + 8) * 20 + c0],     ah[bi][mi][1], al[bi][mi][1]);
            splitu(As[r0 * 20 + c0 + 4],       ah[bi][mi][2], al[bi][mi][2]);
            splitu(As[(r0 + 8) * 20 + c0 + 4], ah[bi][mi][3], al[bi][mi][3]);
        }
        #pragma unroll
        for (int ni = 0; ni < 4; ni++) {
            const int n0 = wn + ni * 8 + g;
            float x0, x1;
            if (TRANSB) {
                x0 = Bs[n0 * 20 + ks + tg];
                x1 = Bs[n0 * 20 + ks + tg + 4];
            } else {
                x0 = Bs[(ks + tg) * 136 + n0];
                x1 = Bs[(ks + tg + 4) * 136 + n0];
            }
            if (TERMS == 3) {
                splitu(x0, bh[bi][ni][0], bl[bi][ni][0]);
                splitu(x1, bh[bi][ni][1], bl[bi][ni][1]);
            } else {
                bh[bi][ni][0] = f2tf32(x0);
                bh[bi][ni][1] = f2tf32(x1);
            }
        }
    };

    auto run_mmas = [&](int bi) {
        #pragma unroll
        for (int mi = 0; mi < 4; mi++)
            #pragma unroll
            for (int ni = 0; ni < 4; ni++) {
                mma8(acc[mi][ni], ah[bi][mi], bh[bi][ni]);
                if (TERMS == 3) mma8(acc[mi][ni], ah[bi][mi], bl[bi][ni]);
                mma8(acc[mi][ni], al[bi][mi], bh[bi][ni]);
            }
    };

    issue(0);
    issue(1);
    cp_wait1();
    __syncthreads();
    load_frags(0, sm + A_OFF(0), sm + B_OFF(0), 0);

    for (int c = 0; c < 64; c++) {
        const float* As = sm + A_OFF(c % STAGES);
        const float* Bs = sm + B_OFF(c % STAGES);
        // step A: prefetch chunk c+2, load ks=8 frags, run ks=0 MMAs
        if (c + 2 < 64) issue(c + 2); else cp_commit();  // uniform group accounting
        load_frags(1, As, Bs, 8);
        run_mmas(0);
        // step B: make stage c+1 visible; prefetch its ks=0 frags; run ks=8 MMAs.
        // The barrier+wait latency is hidden by the 48+ MMAs queued in step A.
        cp_wait1();
        __syncthreads();
        if (c < 63) {
            const int sn = (c + 1) % STAGES;
            load_frags(0, sm + A_OFF(sn), sm + B_OFF(sn), 0);
        }
        run_mmas(1);
    }

    // epilogue: d0,d1 at (g, 2tg..2tg+1), d2,d3 at (g+8, ...)
    #pragma unroll
    for (int mi = 0; mi < 4; mi++) {
        #pragma unroll
        for (int ni = 0; ni < 4; ni++) {
            const int r0 = M0 + wm + mi * 16 + g;
            const int cc = N0 + wn + ni * 8 + 2 * tg;
            float2 v0 = make_float2(acc[mi][ni][0], acc[mi][ni][1]);
            float2 v1 = make_float2(acc[mi][ni][2], acc[mi][ni][3]);
            if (ADDMASK) {
                const float m0v = mp[cc], m1v = mp[cc + 1];
                v0.x += m0v; v0.y += m1v;
                v1.x += m0v; v1.y += m1v;
            }
            *(float2*)(C + (size_t)r0 * NDIM + cc)       = v0;
            *(float2*)(C + (size_t)(r0 + 8) * NDIM + cc) = v1;
        }
    }
}

// In-place row softmax, row length 1024
__global__ __launch_bounds__(256) void softmax_kernel(float* __restrict__ S)
{
    __shared__ float red[8];
    size_t row = blockIdx.x;
    float4* p = reinterpret_cast<float4*>(S + row * 1024);
    int t = threadIdx.x;

    float4 v = p[t];
    float m = fmaxf(fmaxf(v.x, v.y), fmaxf(v.z, v.w));
    #pragma unroll
    for (int o = 16; o; o >>= 1) m = fmaxf(m, __shfl_xor_sync(0xffffffffu, m, o));
    if ((t & 31) == 0) red[t >> 5] = m;
    __syncthreads();
    m = red[0];
    #pragma unroll
    for (int i = 1; i < 8; i++) m = fmaxf(m, red[i]);

    v.x = expf(v.x - m); v.y = expf(v.y - m);
    v.z = expf(v.z - m); v.w = expf(v.w - m);
    float s = v.x + v.y + v.z + v.w;
    #pragma unroll
    for (int o = 16; o; o >>= 1) s += __shfl_xor_sync(0xffffffffu, s, o);
    __syncthreads();
    if ((t & 31) == 0) red[t >> 5] = s;
    __syncthreads();
    s = red[0];
    #pragma unroll
    for (int i = 1; i < 8; i++) s += red[i];

    float inv = 1.0f / s;
    v.x *= inv; v.y *= inv; v.z *= inv; v.w *= inv;
    p[t] = v;
}

extern "C" void kernel_launch(void* const* d_in, const int* in_sizes, int n_in,
                              void* d_out, int out_size)
{
    (void)in_sizes; (void)n_in; (void)out_size;
    const float* query  = (const float*)d_in[0];   // [16,1024,1024]
    const float* keys   = (const float*)d_in[1];   // [16,1024,1024]
    const float* values = (const float*)d_in[2];   // [16,1024,1024]
    const float* W      = (const float*)d_in[3];   // [1024,1024]
    const float* mask   = (const float*)d_in[4];   // [16,1024]

    float* score = (float*)d_out;                        // [16,1024,1024]
    float* ctx   = score + (size_t)16 * 1024 * 1024;     // [16,1024,1024]

    cudaFuncSetAttribute(gemm_tc_kernel<false, false, 3>,
                         cudaFuncAttributeMaxDynamicSharedMemorySize, SMEM_BYTES);
    cudaFuncSetAttribute(gemm_tc_kernel<true, true, 3>,
                         cudaFuncAttributeMaxDynamicSharedMemorySize, SMEM_BYTES);
    cudaFuncSetAttribute(gemm_tc_kernel<false, false, 2>,
                         cudaFuncAttributeMaxDynamicSharedMemorySize, SMEM_BYTES);

    float* qW;
    cudaGetSymbolAddress((void**)&qW, g_qW);

    // qW = query @ W : one 16384x1024x1024 NN GEMM (W batch-shared), 3-term
    gemm_tc_kernel<false, false, 3><<<dim3(8, 128, 1), 256, SMEM_BYTES>>>(
        query, W, qW, nullptr, 0, 0, 0);

    // logits = qW @ keys^T + mask -> score  (NT), 3-term (softmax amplifies logit error)
    gemm_tc_kernel<true, true, 3><<<dim3(8, 8, 16), 256, SMEM_BYTES>>>(
        qW, keys, score, mask, 1048576, 1048576, 1048576);

    // softmax in place over last dim
    softmax_kernel<<<16384, 256>>>(score);

    // ctx = score @ values  (NN), 2-term: full-A x tf32-hi-B, err ~2.8e-4 rel
    gemm_tc_kernel<false, false, 2><<<dim3(8, 8, 16), 256, SMEM_BYTES>>>(
        score, values, ctx, nullptr, 1048576, 1048576, 1048576);
}

// round 5
// speedup vs baseline: 1.9654x; 1.9654x over previous
#include <cuda_runtime.h>
#include <cuda_fp16.h>
#include <cstdint>

// Bilinear attention, B=16, T=D=1024:
//   qW = query @ W ; logits = qW @ keys^T + mask ; score = softmax(logits) ; ctx = score @ values
// GEMMs via mma.sync.m16n8k16 fp16 with error-compensated split
// (Ahi*Bhi + Ahi*Blo + Alo*Bhi, dropped lo*lo ~ 2^-24 rel), fp32 accumulate.
// All GEMMs NT (W and values transposed up front) -> vectorized conflict-free
// float2 fragment loads. 128 threads/CTA, warp tile 64x64, 3-stage cp.async ring.

#define NDIM 1024

// Static scratch (allocation-guard safe)
__device__ float g_qW[16777216];    // 16384 x 1024
__device__ float g_Wt[1048576];     // W^T
__device__ float g_valT[16777216];  // values^T per batch

// ---- helpers -------------------------------------------------------------
static __device__ __forceinline__ uint32_t smem_u32(const void* p) {
    uint32_t a;
    asm("{ .reg .u64 t; cvta.to.shared.u64 t, %1; cvt.u32.u64 %0, t; }" : "=r"(a) : "l"(p));
    return a;
}
static __device__ __forceinline__ uint32_t pack_h2(float lo_elem, float hi_elem) {
    uint32_t r;   // r.lo = f16(lo_elem), r.hi = f16(hi_elem)
    asm("cvt.rn.f16x2.f32 %0, %1, %2;" : "=r"(r) : "f"(hi_elem), "f"(lo_elem));
    return r;
}
// split float2 (elements k, k+1) into hi half2 + lo half2 (mma-ready bit patterns)
static __device__ __forceinline__ void split2(float2 v, uint32_t& h, uint32_t& l) {
    h = pack_h2(v.x, v.y);
    __half2 hh = *reinterpret_cast<__half2*>(&h);
    l = pack_h2(v.x - __low2float(hh), v.y - __high2float(hh));
}
static __device__ __forceinline__ void cpa16(uint32_t dst, const void* src) {
    asm volatile("cp.async.ca.shared.global [%0], [%1], 16;" :: "r"(dst), "l"(src));
}
static __device__ __forceinline__ void cp_commit() {
    asm volatile("cp.async.commit_group;" ::: "memory");
}
static __device__ __forceinline__ void cp_wait2() {
    asm volatile("cp.async.wait_group 2;" ::: "memory");
}
static __device__ __forceinline__ void mma16(float* d, const uint32_t* a, const uint32_t* b) {
    asm volatile(
        "mma.sync.aligned.m16n8k16.row.col.f32.f16.f16.f32 "
        "{%0,%1,%2,%3}, {%4,%5,%6,%7}, {%8,%9}, {%0,%1,%2,%3};"
        : "+f"(d[0]), "+f"(d[1]), "+f"(d[2]), "+f"(d[3])
        : "r"(a[0]), "r"(a[1]), "r"(a[2]), "r"(a[3]), "r"(b[0]), "r"(b[1]));
}

// ---- SMEM: raw f32 tiles, stride 24 floats (96B), 3 stages ---------------
// Stage: A 128x16 @24 (3072 f) + B 128x16 @24 (3072 f)
#define STAGES 3
#define STRIDE 24
#define A_OFF(s) ((s) * 6144)
#define B_OFF(s) ((s) * 6144 + 3072)
static constexpr int SMEM_BYTES = STAGES * 6144 * 4;   // 73728

// TERMS==3: Ahi*Bhi + Ahi*Blo + Alo*Bhi (near-fp32; logit path)
// TERMS==2: Ahi*Bhi + Alo*Bhi            (full-A x f16-B; post-softmax GEMM)
template<bool ADDMASK, int TERMS>
__global__ __launch_bounds__(128) void gemm_fp16_kernel(
    const float* __restrict__ A, const float* __restrict__ B,
    float* __restrict__ C, const float* __restrict__ mask,
    size_t sA, size_t sB, size_t sC)
{
    extern __shared__ float sm[];
    const uint32_t su = smem_u32(sm);
    const int tid = threadIdx.x, wid = tid >> 5, lid = tid & 31;
    const int g = lid >> 2, tg = lid & 3;                  // mma group / thread-in-group
    const int wm = (wid >> 1) * 64, wn = (wid & 1) * 64;   // 2x2 warp grid, 64x64 tiles
    const int M0 = blockIdx.y * 128, N0 = blockIdx.x * 128;
    const size_t b = blockIdx.z;
    A += b * sA; B += b * sB; C += b * sC;
    const float* mp = ADDMASK ? (mask + b * 1024) : nullptr;

    // producer geometry: 128 threads, 4 passes of 32 rows x 16 cols (one 16B ld each)
    const int ar = tid >> 2, acol = (tid & 3) << 2;

    float acc[4][8][4];
    #pragma unroll
    for (int mi = 0; mi < 4; mi++)
        #pragma unroll
        for (int ni = 0; ni < 8; ni++)
            #pragma unroll
            for (int r = 0; r < 4; r++) acc[mi][ni][r] = 0.0f;

    auto issue = [&](int c) {
        const int st = c % STAGES;
        const int k0 = c << 4;
        #pragma unroll
        for (int p = 0; p < 4; p++)
            cpa16(su + (A_OFF(st) + (ar + 32 * p) * STRIDE + acol) * 4,
                  A + (size_t)(M0 + ar + 32 * p) * NDIM + k0 + acol);
        #pragma unroll
        for (int p = 0; p < 4; p++)
            cpa16(su + (B_OFF(st) + (ar + 32 * p) * STRIDE + acol) * 4,
                  B + (size_t)(N0 + ar + 32 * p) * NDIM + k0 + acol);
        cp_commit();
    };

    issue(0);
    issue(1);

    for (int c = 0; c < 64; c++) {
        if (c + 2 < 64) issue(c + 2); else cp_commit();   // uniform group accounting
        cp_wait2();
        __syncthreads();

        const float* As = sm + A_OFF(c % STAGES);
        const float* Bs = sm + B_OFF(c % STAGES);

        uint32_t ah[4][4], al[4][4], bh[8][2], bl[8][2];
        #pragma unroll
        for (int mi = 0; mi < 4; mi++) {
            const int r0 = wm + mi * 16 + g;
            float2 x0 = *(const float2*)&As[r0 * STRIDE + 2 * tg];
            float2 x1 = *(const float2*)&As[(r0 + 8) * STRIDE + 2 * tg];
            float2 x2 = *(const float2*)&As[r0 * STRIDE + 2 * tg + 8];
            float2 x3 = *(const float2*)&As[(r0 + 8) * STRIDE + 2 * tg + 8];
            split2(x0, ah[mi][0], al[mi][0]);
            split2(x1, ah[mi][1], al[mi][1]);
            split2(x2, ah[mi][2], al[mi][2]);
            split2(x3, ah[mi][3], al[mi][3]);
        }
        #pragma unroll
        for (int ni = 0; ni < 8; ni++) {
            const int n0 = wn + ni * 8 + g;
            float2 y0 = *(const float2*)&Bs[n0 * STRIDE + 2 * tg];
            float2 y1 = *(const float2*)&Bs[n0 * STRIDE + 2 * tg + 8];
            if (TERMS == 3) {
                split2(y0, bh[ni][0], bl[ni][0]);
                split2(y1, bh[ni][1], bl[ni][1]);
            } else {
                bh[ni][0] = pack_h2(y0.x, y0.y);
                bh[ni][1] = pack_h2(y1.x, y1.y);
            }
        }
        #pragma unroll
        for (int mi = 0; mi < 4; mi++)
            #pragma unroll
            for (int ni = 0; ni < 8; ni++) {
                mma16(acc[mi][ni], ah[mi], bh[ni]);
                if (TERMS == 3) mma16(acc[mi][ni], ah[mi], bl[ni]);
                mma16(acc[mi][ni], al[mi], bh[ni]);
            }
        __syncthreads();
    }

    // epilogue: d0,d1 at (g, 2tg..2tg+1), d2,d3 at (g+8, ...)
    #pragma unroll
    for (int mi = 0; mi < 4; mi++) {
        #pragma unroll
        for (int ni = 0; ni < 8; ni++) {
            const int r0 = M0 + wm + mi * 16 + g;
            const int cc = N0 + wn + ni * 8 + 2 * tg;
            float2 v0 = make_float2(acc[mi][ni][0], acc[mi][ni][1]);
            float2 v1 = make_float2(acc[mi][ni][2], acc[mi][ni][3]);
            if (ADDMASK) {
                const float m0v = mp[cc], m1v = mp[cc + 1];
                v0.x += m0v; v0.y += m1v;
                v1.x += m0v; v1.y += m1v;
            }
            *(float2*)(C + (size_t)r0 * NDIM + cc)       = v0;
            *(float2*)(C + (size_t)(r0 + 8) * NDIM + cc) = v1;
        }
    }
}

// 1024x1024 f32 transpose (per blockIdx.z slice), block (32,8)
__global__ __launch_bounds__(256) void transpose_kernel(const float* __restrict__ src,
                                                        float* __restrict__ dst)
{
    __shared__ float t[32][33];
    const size_t b = blockIdx.z;
    src += b * 1048576ull; dst += b * 1048576ull;
    const int bx = blockIdx.x * 32, by = blockIdx.y * 32;
    const int x = threadIdx.x, y4 = threadIdx.y * 4;
    #pragma unroll
    for (int i = 0; i < 4; i++)
        t[y4 + i][x] = src[(size_t)(by + y4 + i) * 1024 + bx + x];
    __syncthreads();
    #pragma unroll
    for (int i = 0; i < 4; i++)
        dst[(size_t)(bx + y4 + i) * 1024 + by + x] = t[x][y4 + i];
}

// In-place row softmax, row length 1024
__global__ __launch_bounds__(256) void softmax_kernel(float* __restrict__ S)
{
    __shared__ float red[8];
    size_t row = blockIdx.x;
    float4* p = reinterpret_cast<float4*>(S + row * 1024);
    int t = threadIdx.x;

    float4 v = p[t];
    float m = fmaxf(fmaxf(v.x, v.y), fmaxf(v.z, v.w));
    #pragma unroll
    for (int o = 16; o; o >>= 1) m = fmaxf(m, __shfl_xor_sync(0xffffffffu, m, o));
    if ((t & 31) == 0) red[t >> 5] = m;
    __syncthreads();
    m = red[0];
    #pragma unroll
    for (int i = 1; i < 8; i++) m = fmaxf(m, red[i]);

    v.x = expf(v.x - m); v.y = expf(v.y - m);
    v.z = expf(v.z - m); v.w = expf(v.w - m);
    float s = v.x + v.y + v.z + v.w;
    #pragma unroll
    for (int o = 16; o; o >>= 1) s += __shfl_xor_sync(0xffffffffu, s, o);
    __syncthreads();
    if ((t & 31) == 0) red[t >> 5] = s;
    __syncthreads();
    s = red[0];
    #pragma unroll
    for (int i = 1; i < 8; i++) s += red[i];

    float inv = 1.0f / s;
    v.x *= inv; v.y *= inv; v.z *= inv; v.w *= inv;
    p[t] = v;
}

extern "C" void kernel_launch(void* const* d_in, const int* in_sizes, int n_in,
                              void* d_out, int out_size)
{
    (void)in_sizes; (void)n_in; (void)out_size;
    const float* query  = (const float*)d_in[0];   // [16,1024,1024]
    const float* keys   = (const float*)d_in[1];   // [16,1024,1024]
    const float* values = (const float*)d_in[2];   // [16,1024,1024]
    const float* W      = (const float*)d_in[3];   // [1024,1024]
    const float* mask   = (const float*)d_in[4];   // [16,1024]

    float* score = (float*)d_out;                        // [16,1024,1024]
    float* ctx   = score + (size_t)16 * 1024 * 1024;     // [16,1024,1024]

    cudaFuncSetAttribute(gemm_fp16_kernel<false, 3>,
                         cudaFuncAttributeMaxDynamicSharedMemorySize, SMEM_BYTES);
    cudaFuncSetAttribute(gemm_fp16_kernel<true, 3>,
                         cudaFuncAttributeMaxDynamicSharedMemorySize, SMEM_BYTES);
    cudaFuncSetAttribute(gemm_fp16_kernel<false, 2>,
                         cudaFuncAttributeMaxDynamicSharedMemorySize, SMEM_BYTES);

    float* qW;   cudaGetSymbolAddress((void**)&qW,   g_qW);
    float* Wt;   cudaGetSymbolAddress((void**)&Wt,   g_Wt);
    float* valT; cudaGetSymbolAddress((void**)&valT, g_valT);

    // Prep: W^T and values^T so every GEMM is NT (B consumed [N,K] row-major)
    transpose_kernel<<<dim3(32, 32, 1),  dim3(32, 8)>>>(W, Wt);
    transpose_kernel<<<dim3(32, 32, 16), dim3(32, 8)>>>(values, valT);

    // qW = query @ W : one 16384x1024x1024 NT GEMM (W batch-shared), 3-term
    gemm_fp16_kernel<false, 3><<<dim3(8, 128, 1), 128, SMEM_BYTES>>>(
        query, Wt, qW, nullptr, 0, 0, 0);

    // logits = qW @ keys^T + mask -> score (NT), 3-term (softmax amplifies logit error)
    gemm_fp16_kernel<true, 3><<<dim3(8, 8, 16), 128, SMEM_BYTES>>>(
        qW, keys, score, mask, 1048576, 1048576, 1048576);

    // softmax in place over last dim
    softmax_kernel<<<16384, 256>>>(score);

    // ctx = score @ values (NT on values^T), 2-term: full-A x f16-hi-B (~2e-4 rel)
    gemm_fp16_kernel<false, 2><<<dim3(8, 8, 16), 128, SMEM_BYTES>>>(
        score, valT, ctx, nullptr, 1048576, 1048576, 1048576);
}

// round 6
// speedup vs baseline: 2.2467x; 1.1431x over previous
#include <cuda_runtime.h>
#include <cuda_fp16.h>
#include <cstdint>

// Bilinear attention, B=16, T=D=1024:
//   qW = query @ W ; logits = qW @ keys^T + mask ; score = softmax(logits) ; ctx = score @ values
// GEMMs via mma.sync.m16n8k16 fp16, error-compensated split, fp32 accumulate.
// Producer-side split: raw f32 LDG -> split once -> half2 planes (A-hi/A-lo/B-hi/B-lo)
// in SMEM; consumer fragments are single LDS.32 loads (zero ALU in MMA phase).
// All GEMMs NT (W, values transposed up front). 128 thr/CTA, warp tile 64x64,
// 2-slot plane ring, one barrier per 16-k chunk.

#define NDIM 1024

// Static scratch (allocation-guard safe)
__device__ float g_qW[16777216];    // 16384 x 1024
__device__ float g_Wt[1048576];     // W^T
__device__ float g_valT[16777216];  // values^T per batch

// ---- helpers -------------------------------------------------------------
static __device__ __forceinline__ uint32_t pack_h2(float e0, float e1) {
    uint32_t r;   // r.lo = f16(e0), r.hi = f16(e1)
    asm("cvt.rn.f16x2.f32 %0, %1, %2;" : "=r"(r) : "f"(e1), "f"(e0));
    return r;
}
static __device__ __forceinline__ void split_pair(float x, float y, uint32_t& h, uint32_t& l) {
    h = pack_h2(x, y);
    __half2 hh = *reinterpret_cast<__half2*>(&h);
    l = pack_h2(x - __low2float(hh), y - __high2float(hh));
}
static __device__ __forceinline__ void mma16(float* d, const uint32_t* a, const uint32_t* b) {
    asm volatile(
        "mma.sync.aligned.m16n8k16.row.col.f32.f16.f16.f32 "
        "{%0,%1,%2,%3}, {%4,%5,%6,%7}, {%8,%9}, {%0,%1,%2,%3};"
        : "+f"(d[0]), "+f"(d[1]), "+f"(d[2]), "+f"(d[3])
        : "r"(a[0]), "r"(a[1]), "r"(a[2]), "r"(a[3]), "r"(b[0]), "r"(b[1]));
}

// ---- SMEM plane layout ----------------------------------------------------
// Row = 16 halves data + 8 halves pad = 48 bytes (conflict-free frag LDS + STS).
// Planes per slot: A-hi, A-lo, B-hi, B-lo, each 128 rows x 48B = 6144 B.
#define ROWB 48
#define AH_OFF 0
#define AL_OFF 6144
#define BH_OFF 12288
#define BL_OFF 18432
#define SLOT_BYTES 24576
static constexpr int SMEM_BYTES = 2 * SLOT_BYTES;   // 49152

// TERMS==3: Ahi*Bhi + Ahi*Blo + Alo*Bhi (near-fp32; logit path)
// TERMS==2: Ahi*Bhi + Alo*Bhi            (full-A x f16-B; post-softmax GEMM)
template<bool ADDMASK, int TERMS>
__global__ __launch_bounds__(128) void gemm_fp16_kernel(
    const float* __restrict__ A, const float* __restrict__ B,
    float* __restrict__ C, const float* __restrict__ mask,
    size_t sA, size_t sB, size_t sC)
{
    extern __shared__ __align__(16) char smem[];
    const int tid = threadIdx.x, wid = tid >> 5, lid = tid & 31;
    const int g = lid >> 2, tg = lid & 3;                  // mma group / thread-in-group
    const int wm = (wid >> 1) * 64, wn = (wid & 1) * 64;   // 2x2 warp grid, 64x64 tiles
    const int M0 = blockIdx.y * 128, N0 = blockIdx.x * 128;
    const size_t b = blockIdx.z;
    A += b * sA; B += b * sB; C += b * sC;
    const float* mp = ADDMASK ? (mask + b * 1024) : nullptr;

    // producer geometry: r = row-in-pass (0..31, +32 per pass), q = k-quarter
    const int r = tid >> 2, q = tid & 3;
    const float* Ag = A + (size_t)(M0 + r) * NDIM + 4 * q;
    const float* Bg = B + (size_t)(N0 + r) * NDIM + 4 * q;

    float acc[4][8][4];
    #pragma unroll
    for (int mi = 0; mi < 4; mi++)
        #pragma unroll
        for (int ni = 0; ni < 8; ni++)
            #pragma unroll
            for (int v = 0; v < 4; v++) acc[mi][ni][v] = 0.0f;

    float4 bufA[4], bufB[4];

    auto ldg = [&](int c) {
        const int k0 = c << 4;
        #pragma unroll
        for (int p = 0; p < 4; p++) {
            bufA[p] = *(const float4*)(Ag + (size_t)32 * p * NDIM + k0);
            bufB[p] = *(const float4*)(Bg + (size_t)32 * p * NDIM + k0);
        }
    };

    auto sts = [&](int slot) {
        char* base = smem + slot * SLOT_BYTES;
        #pragma unroll
        for (int p = 0; p < 4; p++) {
            const int ro = (r + 32 * p) * ROWB + q * 8;
            uint32_t h0, h1, l0, l1;
            split_pair(bufA[p].x, bufA[p].y, h0, l0);
            split_pair(bufA[p].z, bufA[p].w, h1, l1);
            *(uint2*)(base + AH_OFF + ro) = make_uint2(h0, h1);
            *(uint2*)(base + AL_OFF + ro) = make_uint2(l0, l1);
            if (TERMS == 3) {
                split_pair(bufB[p].x, bufB[p].y, h0, l0);
                split_pair(bufB[p].z, bufB[p].w, h1, l1);
                *(uint2*)(base + BH_OFF + ro) = make_uint2(h0, h1);
                *(uint2*)(base + BL_OFF + ro) = make_uint2(l0, l1);
            } else {
                h0 = pack_h2(bufB[p].x, bufB[p].y);
                h1 = pack_h2(bufB[p].z, bufB[p].w);
                *(uint2*)(base + BH_OFF + ro) = make_uint2(h0, h1);
            }
        }
    };

    auto frag_mma = [&](int slot) {
        const char* base = smem + slot * SLOT_BYTES;
        // cache all B fragments (n reused over 4 mi)
        uint32_t bh[8][2], bl[8][2];
        #pragma unroll
        for (int ni = 0; ni < 8; ni++) {
            const int n0 = (wn + ni * 8 + g) * ROWB + tg * 4;
            bh[ni][0] = *(const uint32_t*)(base + BH_OFF + n0);
            bh[ni][1] = *(const uint32_t*)(base + BH_OFF + n0 + 16);
            if (TERMS == 3) {
                bl[ni][0] = *(const uint32_t*)(base + BL_OFF + n0);
                bl[ni][1] = *(const uint32_t*)(base + BL_OFF + n0 + 16);
            }
        }
        #pragma unroll
        for (int mi = 0; mi < 4; mi++) {
            const int r0 = (wm + mi * 16 + g) * ROWB + tg * 4;
            const int r1 = r0 + 8 * ROWB;
            uint32_t ah[4], al[4];
            ah[0] = *(const uint32_t*)(base + AH_OFF + r0);
            ah[1] = *(const uint32_t*)(base + AH_OFF + r1);
            ah[2] = *(const uint32_t*)(base + AH_OFF + r0 + 16);
            ah[3] = *(const uint32_t*)(base + AH_OFF + r1 + 16);
            al[0] = *(const uint32_t*)(base + AL_OFF + r0);
            al[1] = *(const uint32_t*)(base + AL_OFF + r1);
            al[2] = *(const uint32_t*)(base + AL_OFF + r0 + 16);
            al[3] = *(const uint32_t*)(base + AL_OFF + r1 + 16);
            #pragma unroll
            for (int ni = 0; ni < 8; ni++) {
                mma16(acc[mi][ni], ah, bh[ni]);
                if (TERMS == 3) mma16(acc[mi][ni], ah, bl[ni]);
                mma16(acc[mi][ni], al, bh[ni]);
            }
        }
    };

    // prologue: fill slot 0
    ldg(0);
    sts(0);
    __syncthreads();

    for (int c = 0; c < 64; c++) {
        if (c + 1 < 64) ldg(c + 1);       // in flight during MMA phase
        frag_mma(c & 1);
        if (c + 1 < 64) sts((c + 1) & 1); // slot was drained in iter c-1 (bar'ed)
        __syncthreads();
    }

    // epilogue: d0,d1 at (g, 2tg..2tg+1), d2,d3 at (g+8, ...)
    #pragma unroll
    for (int mi = 0; mi < 4; mi++) {
        #pragma unroll
        for (int ni = 0; ni < 8; ni++) {
            const int r0 = M0 + wm + mi * 16 + g;
            const int cc = N0 + wn + ni * 8 + 2 * tg;
            float2 v0 = make_float2(acc[mi][ni][0], acc[mi][ni][1]);
            float2 v1 = make_float2(acc[mi][ni][2], acc[mi][ni][3]);
            if (ADDMASK) {
                const float m0v = mp[cc], m1v = mp[cc + 1];
                v0.x += m0v; v0.y += m1v;
                v1.x += m0v; v1.y += m1v;
            }
            *(float2*)(C + (size_t)r0 * NDIM + cc)       = v0;
            *(float2*)(C + (size_t)(r0 + 8) * NDIM + cc) = v1;
        }
    }
}

// 1024x1024 f32 transpose (per blockIdx.z slice), block (32,8)
__global__ __launch_bounds__(256) void transpose_kernel(const float* __restrict__ src,
                                                        float* __restrict__ dst)
{
    __shared__ float t[32][33];
    const size_t b = blockIdx.z;
    src += b * 1048576ull; dst += b * 1048576ull;
    const int bx = blockIdx.x * 32, by = blockIdx.y * 32;
    const int x = threadIdx.x, y4 = threadIdx.y * 4;
    #pragma unroll
    for (int i = 0; i < 4; i++)
        t[y4 + i][x] = src[(size_t)(by + y4 + i) * 1024 + bx + x];
    __syncthreads();
    #pragma unroll
    for (int i = 0; i < 4; i++)
        dst[(size_t)(bx + y4 + i) * 1024 + by + x] = t[x][y4 + i];
}

// In-place row softmax, row length 1024
__global__ __launch_bounds__(256) void softmax_kernel(float* __restrict__ S)
{
    __shared__ float red[8];
    size_t row = blockIdx.x;
    float4* p = reinterpret_cast<float4*>(S + row * 1024);
    int t = threadIdx.x;

    float4 v = p[t];
    float m = fmaxf(fmaxf(v.x, v.y), fmaxf(v.z, v.w));
    #pragma unroll
    for (int o = 16; o; o >>= 1) m = fmaxf(m, __shfl_xor_sync(0xffffffffu, m, o));
    if ((t & 31) == 0) red[t >> 5] = m;
    __syncthreads();
    m = red[0];
    #pragma unroll
    for (int i = 1; i < 8; i++) m = fmaxf(m, red[i]);

    v.x = expf(v.x - m); v.y = expf(v.y - m);
    v.z = expf(v.z - m); v.w = expf(v.w - m);
    float s = v.x + v.y + v.z + v.w;
    #pragma unroll
    for (int o = 16; o; o >>= 1) s += __shfl_xor_sync(0xffffffffu, s, o);
    __syncthreads();
    if ((t & 31) == 0) red[t >> 5] = s;
    __syncthreads();
    s = red[0];
    #pragma unroll
    for (int i = 1; i < 8; i++) s += red[i];

    float inv = 1.0f / s;
    v.x *= inv; v.y *= inv; v.z *= inv; v.w *= inv;
    p[t] = v;
}

extern "C" void kernel_launch(void* const* d_in, const int* in_sizes, int n_in,
                              void* d_out, int out_size)
{
    (void)in_sizes; (void)n_in; (void)out_size;
    const float* query  = (const float*)d_in[0];   // [16,1024,1024]
    const float* keys   = (const float*)d_in[1];   // [16,1024,1024]
    const float* values = (const float*)d_in[2];   // [16,1024,1024]
    const float* W      = (const float*)d_in[3];   // [1024,1024]
    const float* mask   = (const float*)d_in[4];   // [16,1024]

    float* score = (float*)d_out;                        // [16,1024,1024]
    float* ctx   = score + (size_t)16 * 1024 * 1024;     // [16,1024,1024]

    cudaFuncSetAttribute(gemm_fp16_kernel<false, 3>,
                         cudaFuncAttributeMaxDynamicSharedMemorySize, SMEM_BYTES);
    cudaFuncSetAttribute(gemm_fp16_kernel<true, 3>,
                         cudaFuncAttributeMaxDynamicSharedMemorySize, SMEM_BYTES);
    cudaFuncSetAttribute(gemm_fp16_kernel<false, 2>,
                         cudaFuncAttributeMaxDynamicSharedMemorySize, SMEM_BYTES);

    float* qW;   cudaGetSymbolAddress((void**)&qW,   g_qW);
    float* Wt;   cudaGetSymbolAddress((void**)&Wt,   g_Wt);
    float* valT; cudaGetSymbolAddress((void**)&valT, g_valT);

    // Prep: W^T and values^T so every GEMM is NT (B consumed [N,K] row-major)
    transpose_kernel<<<dim3(32, 32, 1),  dim3(32, 8)>>>(W, Wt);
    transpose_kernel<<<dim3(32, 32, 16), dim3(32, 8)>>>(values, valT);

    // qW = query @ W : one 16384x1024x1024 NT GEMM (W batch-shared), 3-term
    gemm_fp16_kernel<false, 3><<<dim3(8, 128, 1), 128, SMEM_BYTES>>>(
        query, Wt, qW, nullptr, 0, 0, 0);

    // logits = qW @ keys^T + mask -> score (NT), 3-term (softmax amplifies logit error)
    gemm_fp16_kernel<true, 3><<<dim3(8, 8, 16), 128, SMEM_BYTES>>>(
        qW, keys, score, mask, 1048576, 1048576, 1048576);

    // softmax in place over last dim
    softmax_kernel<<<16384, 256>>>(score);

    // ctx = score @ values (NT on values^T), 2-term: full-A x f16-hi-B (~2e-4 rel)
    gemm_fp16_kernel<false, 2><<<dim3(8, 8, 16), 128, SMEM_BYTES>>>(
        score, valT, ctx, nullptr, 1048576, 1048576, 1048576);
}